// round 14
// baseline (speedup 1.0000x reference)
#include <cuda_runtime.h>
#include <cuda_fp16.h>
#include <math.h>

#define BATCH 4
#define LQ 2048
#define LK 2048
#define DMODEL 512
#define NH 2
#define DK 64
#define DV 64
#define QKV_N 128
#define BH (BATCH * NH)

#define BQ 128
#define BK 64
#define NSPLIT 2
#define KSPAN (LK / NSPLIT)     // 1024
#define NCH (KSPAN / BK)        // 16 chunks per CTA

// smem layout (float indices)
#define OFF_Q 0                 // f32 [64d][128q]            8192
#define OFF_K16 8192            // fp16 2 x [64d][64k]        4096 (floats)
#define OFF_V16 12288           // fp16 2 x [64k][64dv]       4096
#define OFF_S 16384             // f32 [64k][128q]            8192
#define OFF_RL 24576            // 128
#define OFF_MSK 24704           // 2 x 64
#define SMEM_FLOATS 24832
#define SMEM_BYTES (SMEM_FLOATS * 4)   // 99328 -> 2 CTAs/SM

#define SVP_SZ (BATCH * LQ * QKV_N)    // per-split partial SV floats

typedef unsigned long long ull;

__device__ __forceinline__ ull pk2(float x, float y)
{ ull r; asm("mov.b64 %0,{%1,%2};" : "=l"(r) : "f"(x), "f"(y)); return r; }
__device__ __forceinline__ ull bc2(float x) { return pk2(x, x); }
__device__ __forceinline__ void fma2(ull& d, ull a, ull b)
{ asm("fma.rn.f32x2 %0,%1,%2,%0;" : "+l"(d) : "l"(a), "l"(b)); }
__device__ __forceinline__ float2 up2(ull v)
{ float2 r; asm("mov.b64 {%0,%1},%2;" : "=f"(r.x), "=f"(r.y) : "l"(v)); return r; }

__device__ __forceinline__ unsigned smem_u32(const void* p)
{
    unsigned a;
    asm("{ .reg .u64 t; cvta.to.shared.u64 t, %1; cvt.u32.u64 %0, t; }"
        : "=r"(a) : "l"(p));
    return a;
}
__device__ __forceinline__ void cp_async16(unsigned dst, const void* src)
{ asm volatile("cp.async.cg.shared.global [%0],[%1],16;" :: "r"(dst), "l"(src)); }
__device__ __forceinline__ void cp_commit()
{ asm volatile("cp.async.commit_group;"); }
__device__ __forceinline__ void cp_wait0()
{ asm volatile("cp.async.wait_group 0;"); }

__device__ __forceinline__ void st_cs4(float* p, float4 v)
{ asm volatile("st.global.cs.v4.f32 [%0],{%1,%2,%3,%4};"
               :: "l"(p), "f"(v.x), "f"(v.y), "f"(v.z), "f"(v.w) : "memory"); }
__device__ __forceinline__ float4 ld_cs4(const float* p)
{
    float4 v;
    asm volatile("ld.global.cs.v4.f32 {%0,%1,%2,%3},[%4];"
                 : "=f"(v.x), "=f"(v.y), "=f"(v.z), "=f"(v.w) : "l"(p));
    return v;
}

__device__ __forceinline__ float2 h2f(unsigned u)
{ __half2 h = *(__half2*)&u; return __half22float2(h); }
__device__ __forceinline__ unsigned f2h2(float a, float b)
{ __half2 h = __floats2half2_rn(a, b); return *(unsigned*)&h; }

__device__ __forceinline__ int s_off(int kc, int g)
{ return OFF_S + kc * 128 + (((g + kc + (kc >> 3)) & 31) << 2); }

// 10*tanh(0.125*x) = 10 - 20/(exp(0.25x)+1); exact at +/-inf
__device__ __forceinline__ float tanh10s(float x)
{
    float e = __expf(0.25f * x);
    float r;
    asm("rcp.approx.f32 %0,%1;" : "=f"(r) : "f"(e + 1.f));
    return fmaf(-20.f, r, 10.f);
}

__device__ float g_qT[BATCH * QKV_N * LQ];     // f32 transposed
__device__ __half g_k16[BATCH * QKV_N * LK];   // fp16 transposed [b*128+col][l]
__device__ __half g_v16[BATCH * LK * QKV_N];   // fp16 natural
__device__ float g_svp[NSPLIT * SVP_SZ];       // partial SV
__device__ float g_rlp[NSPLIT * BH * LQ];      // partial sum-exp
__device__ float g_otmp[BATCH * LQ * QKV_N];
__device__ float g_vsum[BH * DV];
__device__ float g_lse[BH * LQ];
__device__ int g_mask_mode;

__device__ __forceinline__ float mask_at(const void* p, int mode, size_t gi)
{
    if (mode == 1) return ((const int*)p)[gi] != 0 ? 1.f : 0.f;
    if (mode == 0) return ((const unsigned char*)p)[gi] != 0 ? 1.f : 0.f;
    return ((const float*)p)[gi] != 0.f ? 1.f : 0.f;
}

__global__ void detect_mask_kernel(const unsigned int* __restrict__ w)
{
    __shared__ int s_f32, s_all01;
    if (threadIdx.x == 0) { s_f32 = 0; s_all01 = 1; }
    __syncthreads();
    int f = 0, bad = 0;
    for (int i = threadIdx.x; i < 2048; i += blockDim.x) {
        unsigned v = w[i];
        if (v == 0x3F800000u) f = 1;
        if (v > 1u) bad = 1;
    }
    if (f) atomicOr(&s_f32, 1);
    if (bad) atomicExch(&s_all01, 0);
    __syncthreads();
    if (threadIdx.x == 0) g_mask_mode = s_f32 ? 2 : (s_all01 ? 1 : 0);
}

// ---- fused QKV projection: 64x128 tile, 128 threads, 8x8 frags.
// sel 0 (Q): f32 transposed. sel 1 (K): fp16 transposed. sel 2 (V): fp16 natural.
__global__ __launch_bounds__(128) void gemm_qkv_kernel(
    const float* __restrict__ X0, const float* __restrict__ X1, const float* __restrict__ X2,
    const float* __restrict__ W0, const float* __restrict__ W1, const float* __restrict__ W2,
    const float* __restrict__ B0, const float* __restrict__ B1, const float* __restrict__ B2,
    float* __restrict__ YQ, __half* __restrict__ YK, __half* __restrict__ YV)
{
    __shared__ float xs[32 * 68];
    __shared__ float ws[32 * 132];
    int sel = blockIdx.y;
    const float* X = sel == 0 ? X0 : (sel == 1 ? X1 : X2);
    const float* W = sel == 0 ? W0 : (sel == 1 ? W1 : W2);
    const float* bias = sel == 0 ? B0 : (sel == 1 ? B1 : B2);

    int tid = threadIdx.x;
    int tx = tid & 15, ty = tid >> 4;
    int bm = blockIdx.x * 64;
    int row0 = ty * 8, col0 = tx * 8;

    ull acc2[4][8];
#pragma unroll
    for (int p = 0; p < 4; p++)
#pragma unroll
        for (int j = 0; j < 8; j++) acc2[p][j] = 0ull;

    for (int k0 = 0; k0 < DMODEL; k0 += 32) {
#pragma unroll
        for (int i = 0; i < 4; i++) {
            int linear = tid + i * 128;
            int m = linear >> 3;
            int g = (linear & 7) * 4;
            float4 v = *(const float4*)&X[(size_t)(bm + m) * DMODEL + k0 + g];
            xs[(g + 0) * 68 + m] = v.x;
            xs[(g + 1) * 68 + m] = v.y;
            xs[(g + 2) * 68 + m] = v.z;
            xs[(g + 3) * 68 + m] = v.w;
        }
#pragma unroll
        for (int i = 0; i < 8; i++) {
            int linear = tid + i * 128;
            int k = linear >> 5;
            int g = (linear & 31) * 4;
            *(float4*)&ws[k * 132 + g] = *(const float4*)&W[(size_t)(k0 + k) * QKV_N + g];
        }
        __syncthreads();
#pragma unroll
        for (int k = 0; k < 32; k++) {
            float4 xa = *(const float4*)&xs[k * 68 + row0];
            float4 xb = *(const float4*)&xs[k * 68 + row0 + 4];
            float4 wa = *(const float4*)&ws[k * 132 + col0];
            float4 wb = *(const float4*)&ws[k * 132 + col0 + 4];
            ull xp[4] = {pk2(xa.x, xa.y), pk2(xa.z, xa.w),
                         pk2(xb.x, xb.y), pk2(xb.z, xb.w)};
            ull wn[8] = {bc2(wa.x), bc2(wa.y), bc2(wa.z), bc2(wa.w),
                         bc2(wb.x), bc2(wb.y), bc2(wb.z), bc2(wb.w)};
#pragma unroll
            for (int p = 0; p < 4; p++)
#pragma unroll
                for (int j = 0; j < 8; j++)
                    fma2(acc2[p][j], xp[p], wn[j]);
        }
        __syncthreads();
    }
    float bb[8];
#pragma unroll
    for (int j = 0; j < 8; j++) bb[j] = bias[col0 + j];

    float y[8][8];
#pragma unroll
    for (int p = 0; p < 4; p++)
#pragma unroll
        for (int j = 0; j < 8; j++) {
            float2 t = up2(acc2[p][j]);
            y[2 * p][j] = t.x + bb[j];
            y[2 * p + 1][j] = t.y + bb[j];
        }

    int b = bm >> 11;
    int l0 = (bm & 2047) + row0;

    if (sel == 0) {          // Q f32 transposed
#pragma unroll
        for (int j = 0; j < 8; j++) {
            float* yp = &YQ[((size_t)(b * QKV_N + col0 + j)) * LQ + l0];
            *(float4*)yp = make_float4(y[0][j], y[1][j], y[2][j], y[3][j]);
            *(float4*)(yp + 4) = make_float4(y[4][j], y[5][j], y[6][j], y[7][j]);
        }
    } else if (sel == 1) {   // K fp16 transposed
#pragma unroll
        for (int j = 0; j < 8; j++) {
            unsigned hv[4];
#pragma unroll
            for (int r = 0; r < 8; r += 2)
                hv[r >> 1] = f2h2(y[r][j], y[r + 1][j]);
            *(uint4*)&YK[((size_t)(b * QKV_N + col0 + j)) * LK + l0] =
                make_uint4(hv[0], hv[1], hv[2], hv[3]);
        }
    } else {                 // V fp16 natural
#pragma unroll
        for (int r = 0; r < 8; r++) {
            unsigned hv[4];
#pragma unroll
            for (int j = 0; j < 8; j += 2)
                hv[j >> 1] = f2h2(y[r][j], y[r][j + 1]);
            *(uint4*)&YV[(size_t)(bm + row0 + r) * QKV_N + col0] =
                make_uint4(hv[0], hv[1], hv[2], hv[3]);
        }
    }
}

// ---- out-proj GEMM, 128x128 tile, 8x8 frags
__global__ __launch_bounds__(256) void gemm_bias128_kernel(
    const float* __restrict__ X, const float* __restrict__ W,
    const float* __restrict__ bias, float* __restrict__ Y,
    int M, int K, int N)
{
    __shared__ float xs[32 * 132];
    __shared__ float ws[32 * 132];
    int tid = threadIdx.x;
    int tx = tid & 15, ty = tid >> 4;
    int bm = blockIdx.x * 128, bn = blockIdx.y * 128;
    int row0 = ty * 8, col0 = tx * 8;

    ull acc2[4][8];
#pragma unroll
    for (int p = 0; p < 4; p++)
#pragma unroll
        for (int j = 0; j < 8; j++) acc2[p][j] = 0ull;

    for (int k0 = 0; k0 < K; k0 += 32) {
#pragma unroll
        for (int i = 0; i < 4; i++) {
            int linear = tid + i * 256;
            int m = linear >> 3;
            int g = (linear & 7) * 4;
            float4 v = *(const float4*)&X[(size_t)(bm + m) * K + k0 + g];
            xs[(g + 0) * 132 + m] = v.x;
            xs[(g + 1) * 132 + m] = v.y;
            xs[(g + 2) * 132 + m] = v.z;
            xs[(g + 3) * 132 + m] = v.w;
        }
#pragma unroll
        for (int i = 0; i < 4; i++) {
            int linear = tid + i * 256;
            int k = linear >> 5;
            int g = (linear & 31) * 4;
            *(float4*)&ws[k * 132 + g] = *(const float4*)&W[(size_t)(k0 + k) * N + bn + g];
        }
        __syncthreads();
#pragma unroll
        for (int k = 0; k < 32; k++) {
            float4 xa = *(const float4*)&xs[k * 132 + row0];
            float4 xb = *(const float4*)&xs[k * 132 + row0 + 4];
            float4 wa = *(const float4*)&ws[k * 132 + col0];
            float4 wb = *(const float4*)&ws[k * 132 + col0 + 4];
            ull xp[4] = {pk2(xa.x, xa.y), pk2(xa.z, xa.w),
                         pk2(xb.x, xb.y), pk2(xb.z, xb.w)};
            ull wn[8] = {bc2(wa.x), bc2(wa.y), bc2(wa.z), bc2(wa.w),
                         bc2(wb.x), bc2(wb.y), bc2(wb.z), bc2(wb.w)};
#pragma unroll
            for (int p = 0; p < 4; p++)
#pragma unroll
                for (int j = 0; j < 8; j++)
                    fma2(acc2[p][j], xp[p], wn[j]);
        }
        __syncthreads();
    }
    float bb[8];
#pragma unroll
    for (int j = 0; j < 8; j++) bb[j] = bias[bn + col0 + j];
#pragma unroll
    for (int p = 0; p < 4; p++) {
        float r0[8], r1[8];
#pragma unroll
        for (int j = 0; j < 8; j++) {
            float2 t = up2(acc2[p][j]);
            r0[j] = t.x + bb[j];
            r1[j] = t.y + bb[j];
        }
        float* y0 = &Y[(size_t)(bm + row0 + 2 * p) * N + bn + col0];
        *(float4*)y0 = make_float4(r0[0], r0[1], r0[2], r0[3]);
        *(float4*)(y0 + 4) = make_float4(r0[4], r0[5], r0[6], r0[7]);
        float* y1 = y0 + N;
        *(float4*)y1 = make_float4(r1[0], r1[1], r1[2], r1[3]);
        *(float4*)(y1 + 4) = make_float4(r1[4], r1[5], r1[6], r1[7]);
    }
}

__global__ void vsum_zero_kernel() { g_vsum[threadIdx.x] = 0.f; }

// column sums of fp16 V
__global__ __launch_bounds__(256) void vsum_kernel()
{
    __shared__ float red[8][128];
    int b = blockIdx.x, part = blockIdx.y;
    int c4 = (threadIdx.x & 31) * 4;
    int r0 = threadIdx.x >> 5;
    const __half* base = g_v16 + ((size_t)b * LK + part * 128) * QKV_N;
    float4 s = make_float4(0.f, 0.f, 0.f, 0.f);
#pragma unroll 4
    for (int r = r0; r < 128; r += 8) {
        uint2 u = *(const uint2*)&base[(size_t)r * QKV_N + c4];
        float2 a = h2f(u.x), c = h2f(u.y);
        s.x += a.x; s.y += a.y; s.z += c.x; s.w += c.y;
    }
    *(float4*)&red[r0][c4] = s;
    __syncthreads();
    if (threadIdx.x < 128) {
        float t = 0.f;
#pragma unroll
        for (int i = 0; i < 8; i++) t += red[i][threadIdx.x];
        atomicAdd(&g_vsum[b * QKV_N + threadIdx.x], t);
    }
}

// combine kv-split partials: lse, otmp
__global__ __launch_bounds__(256) void combine_kernel()
{
    int row = blockIdx.x * 2 + (threadIdx.x >> 7);   // b*2048+q, 8192 rows
    int col = threadIdx.x & 127;
    int b = row >> 11, q = row & 2047;
    int hh = col >> 6;
    int bhq = (b * NH + hh) * LQ + q;
    float rl = g_rlp[bhq] + g_rlp[BH * LQ + bhq];
    float l = logf(rl);
    if ((col & 63) == 0) g_lse[bhq] = l;
    size_t o = (size_t)row * QKV_N + col;
    g_otmp[o] = g_svp[o] + g_svp[SVP_SZ + o]
              - l * g_vsum[(b * NH + hh) * DV + (col & 63)];
}

// streaming lse fix-up: attn[row][*] -= lse[row]
__global__ __launch_bounds__(256) void lse_fix_kernel(float* __restrict__ attn)
{
    int row = blockIdx.x * 2 + (threadIdx.x >> 7);
    int lane = threadIdx.x & 127;
    float l = g_lse[row];
    float* p = attn + (size_t)row * LK;
#pragma unroll
    for (int j = 0; j < 4; j++) {
        float* q = p + (lane + j * 128) * 4;
        float4 a = ld_cs4(q);
        a.x -= l; a.y -= l; a.z -= l; a.w -= l;
        st_cs4(q, a);
    }
}

// main: 1 CTA = 128 q x 1024 keys (split) for one (b,h); fp16 K/V, 2 CTAs/SM
__global__ __launch_bounds__(256, 2) void mab_main_kernel(
    const void* __restrict__ maskp, float* __restrict__ attn)
{
    extern __shared__ float sm[];
    __half* khalf = (__half*)(sm + OFF_K16);
    __half* vhalf = (__half*)(sm + OFF_V16);
    int tid = threadIdx.x;
    int tx = tid & 15, ty = tid >> 4;
    int m0 = ty * 8;
    int nk = tx * 4;
    int nv = tx * 4;
    int q0 = blockIdx.x * BQ;
    int h = blockIdx.y;
    int b = blockIdx.z >> 1;
    int split = blockIdx.z & 1;
    int ks0 = split * KSPAN;
    int bh = b * NH + h;
    int mode = g_mask_mode;

    const float* qtbase = g_qT + ((size_t)(b * QKV_N + h * DK)) * LQ + q0;
    const __half* ktb = g_k16 + ((size_t)(b * QKV_N + h * DK)) * LK;
    const __half* vtb = g_v16 + (size_t)b * LK * QKV_N + h * DK;
    float* arow = attn + ((size_t)(bh * LQ + q0)) * LK;

    // prologue: Q + K(0) + V(0)
#pragma unroll
    for (int i = 0; i < 8; i++) {
        int lin = tid + i * 256;
        int d = lin >> 5, qq = (lin & 31) * 4;
        cp_async16(smem_u32(&sm[OFF_Q + d * 128 + qq]), &qtbase[(size_t)d * LQ + qq]);
    }
#pragma unroll
    for (int i = 0; i < 2; i++) {
        int lin = tid + i * 256;
        int d = lin >> 3, kk = (lin & 7) * 8;
        cp_async16(smem_u32(&khalf[d * 64 + kk]), &ktb[(size_t)d * LK + ks0 + kk]);
    }
#pragma unroll
    for (int i = 0; i < 2; i++) {
        int lin = tid + i * 256;
        int kr = lin >> 3, dv = (lin & 7) * 8;
        cp_async16(smem_u32(&vhalf[kr * 64 + dv]),
                   &vtb[(size_t)(ks0 + kr) * QKV_N + dv]);
    }
    cp_commit();
    float mreg = 0.f;
    if (tid < BK) mreg = mask_at(maskp, mode, (size_t)b * LK + ks0 + tid);
    if (tid < BQ) sm[OFF_RL + tid] = 0.f;

    ull sv2[4][4];
#pragma unroll
    for (int i = 0; i < 4; i++)
#pragma unroll
        for (int j = 0; j < 4; j++) sv2[i][j] = 0ull;

    for (int c = 0; c < NCH; c++) {
        int k0 = ks0 + c * BK;
        int kb = (c & 1) * 2048;         // half-index offset (2048 floats worth/2)
        int khb = (c & 1) * 4096;        // halfs per K buffer
        int vhb = (c & 1) * 4096;
        int mbuf = OFF_MSK + (c & 1) * 64;
        if (tid < BK) sm[mbuf + tid] = mreg;
        cp_wait0();
        __syncthreads();                 // B
        (void)kb;

        if (c < NCH - 1) {
            int k1 = k0 + BK;
            int khn = ((c + 1) & 1) * 4096;
            int vhn = ((c + 1) & 1) * 4096;
#pragma unroll
            for (int i = 0; i < 2; i++) {
                int lin = tid + i * 256;
                int d = lin >> 3, kk = (lin & 7) * 8;
                cp_async16(smem_u32(&khalf[khn + d * 64 + kk]),
                           &ktb[(size_t)d * LK + k1 + kk]);
            }
#pragma unroll
            for (int i = 0; i < 2; i++) {
                int lin = tid + i * 256;
                int kr = lin >> 3, dv = (lin & 7) * 8;
                cp_async16(smem_u32(&vhalf[vhn + kr * 64 + dv]),
                           &vtb[(size_t)(k1 + kr) * QKV_N + dv]);
            }
            cp_commit();
            if (tid < BK) mreg = mask_at(maskp, mode, (size_t)b * LK + k1 + tid);
        }

        // phase 1: S = q@k^T, 8q x 4k per thread
        ull acc2[4][4];
#pragma unroll
        for (int p = 0; p < 4; p++)
#pragma unroll
            for (int j = 0; j < 4; j++) acc2[p][j] = 0ull;

#pragma unroll 4
        for (int d = 0; d < DK; d++) {
            float4 qa = *(const float4*)&sm[OFF_Q + d * 128 + m0];
            float4 qb = *(const float4*)&sm[OFF_Q + d * 128 + m0 + 4];
            uint2 ku = *(const uint2*)&khalf[khb + d * 64 + nk];
            float2 k01 = h2f(ku.x), k23 = h2f(ku.y);
            ull qp[4] = {pk2(qa.x, qa.y), pk2(qa.z, qa.w),
                         pk2(qb.x, qb.y), pk2(qb.z, qb.w)};
            ull kbv[4] = {bc2(k01.x), bc2(k01.y), bc2(k23.x), bc2(k23.y)};
#pragma unroll
            for (int p = 0; p < 4; p++)
#pragma unroll
                for (int j = 0; j < 4; j++)
                    fma2(acc2[p][j], qp[p], kbv[j]);
        }

        float acc[8][4];
#pragma unroll
        for (int p = 0; p < 4; p++)
#pragma unroll
            for (int j = 0; j < 4; j++) {
                float2 v = up2(acc2[p][j]);
                acc[2 * p][j] = v.x;
                acc[2 * p + 1][j] = v.y;
            }

        float mk[4];
#pragma unroll
        for (int j = 0; j < 4; j++) mk[j] = sm[mbuf + nk + j];

        float er[8];
#pragma unroll
        for (int i = 0; i < 8; i++) {
            float rs = 0.f;
#pragma unroll
            for (int j = 0; j < 4; j++) {
                float s = tanh10s(acc[i][j]);
                if (mk[j] != 0.f) s = -10.f;
                acc[i][j] = s;
                rs += __expf(s);
            }
            er[i] = rs;
            st_cs4(&arow[(size_t)(m0 + i) * LK + k0 + nk],
                   make_float4(acc[i][0], acc[i][1], acc[i][2], acc[i][3]));
        }
#pragma unroll
        for (int d = 1; d < 16; d <<= 1) {
#pragma unroll
            for (int i = 0; i < 8; i++)
                er[i] += __shfl_xor_sync(0xffffffffu, er[i], d);
        }
        if (tx == 0) {
#pragma unroll
            for (int i = 0; i < 8; i++)
                sm[OFF_RL + m0 + i] += er[i];
        }
        {
            int g = m0 >> 2;
#pragma unroll
            for (int j = 0; j < 4; j++) {
                int kc = nk + j;
                *(float4*)&sm[s_off(kc, g)] =
                    make_float4(acc[0][j], acc[1][j], acc[2][j], acc[3][j]);
                *(float4*)&sm[s_off(kc, g + 1)] =
                    make_float4(acc[4][j], acc[5][j], acc[6][j], acc[7][j]);
            }
        }
        __syncthreads();   // C

        // phase 2: SV += S @ V, 8q x 4dv per thread
        {
            int g = m0 >> 2;
#pragma unroll 8
            for (int kc = 0; kc < BK; kc++) {
                float4 sa = *(const float4*)&sm[s_off(kc, g)];
                float4 sb = *(const float4*)&sm[s_off(kc, g + 1)];
                uint2 vu = *(const uint2*)&vhalf[vhb + kc * 64 + nv];
                float2 v01 = h2f(vu.x), v23 = h2f(vu.y);
                ull sp[4] = {pk2(sa.x, sa.y), pk2(sa.z, sa.w),
                             pk2(sb.x, sb.y), pk2(sb.z, sb.w)};
                ull vb[4] = {bc2(v01.x), bc2(v01.y), bc2(v23.x), bc2(v23.y)};
#pragma unroll
                for (int p = 0; p < 4; p++)
#pragma unroll
                    for (int j = 0; j < 4; j++)
                        fma2(sv2[p][j], sp[p], vb[j]);
            }
        }
    }

    __syncthreads();
    if (tid < BQ)
        g_rlp[split * BH * LQ + bh * LQ + q0 + tid] = sm[OFF_RL + tid];

    {   // partial SV store (no lse here)
        float* svb = g_svp + (size_t)split * SVP_SZ;
#pragma unroll
        for (int p = 0; p < 4; p++) {
            float2 c0 = up2(sv2[p][0]), c1 = up2(sv2[p][1]);
            float2 c2 = up2(sv2[p][2]), c3 = up2(sv2[p][3]);
            size_t r0 = ((size_t)b * LQ + q0 + m0 + 2 * p) * QKV_N + h * DK + nv;
            *(float4*)&svb[r0] = make_float4(c0.x, c1.x, c2.x, c3.x);
            *(float4*)&svb[r0 + QKV_N] = make_float4(c0.y, c1.y, c2.y, c3.y);
        }
    }
}

extern "C" void kernel_launch(void* const* d_in, const int* in_sizes, int n_in,
                              void* d_out, int out_size)
{
    const float* Q  = (const float*)d_in[0];
    const float* K  = (const float*)d_in[1];
    const float* V  = (const float*)d_in[2];
    const void*  Mk = d_in[3];
    const float* Wq = (const float*)d_in[4];
    const float* bq = (const float*)d_in[5];
    const float* Wk = (const float*)d_in[6];
    const float* bk = (const float*)d_in[7];
    const float* Wv = (const float*)d_in[8];
    const float* bv = (const float*)d_in[9];
    const float* Wo = (const float*)d_in[10];
    const float* bo = (const float*)d_in[11];

    float* out  = (float*)d_out;
    float* attn = out + (size_t)BATCH * LQ * DMODEL;

    float *gqt, *gotmp;
    __half *gk16, *gv16;
    cudaGetSymbolAddress((void**)&gqt, g_qT);
    cudaGetSymbolAddress((void**)&gk16, g_k16);
    cudaGetSymbolAddress((void**)&gv16, g_v16);
    cudaGetSymbolAddress((void**)&gotmp, g_otmp);

    static int inited = 0;
    static cudaStream_t s2;
    static cudaEvent_t e1, e2, e3, e4;
    if (!inited) {
        cudaFuncSetAttribute(mab_main_kernel,
                             cudaFuncAttributeMaxDynamicSharedMemorySize, SMEM_BYTES);
        cudaStreamCreateWithFlags(&s2, cudaStreamNonBlocking);
        cudaEventCreateWithFlags(&e1, cudaEventDisableTiming);
        cudaEventCreateWithFlags(&e2, cudaEventDisableTiming);
        cudaEventCreateWithFlags(&e3, cudaEventDisableTiming);
        cudaEventCreateWithFlags(&e4, cudaEventDisableTiming);
        inited = 1;
    }

    detect_mask_kernel<<<1, 256>>>((const unsigned int*)Mk);

    const int M = BATCH * LQ;  // 8192
    gemm_qkv_kernel<<<dim3(M / 64, 3), 128>>>(Q, K, V, Wq, Wk, Wv,
                                              bq, bk, bv, gqt, gk16, gv16);

    // vsum runs on side stream, parallel to main (main no longer reads vsum)
    cudaEventRecord(e1, 0);
    cudaStreamWaitEvent(s2, e1, 0);
    vsum_zero_kernel<<<1, BH * DV, 0, s2>>>();
    vsum_kernel<<<dim3(BATCH, 16), 256, 0, s2>>>();
    cudaEventRecord(e2, s2);

    mab_main_kernel<<<dim3(LQ / BQ, NH, BATCH * NSPLIT), 256, SMEM_BYTES>>>(Mk, attn);

    cudaStreamWaitEvent(0, e2, 0);
    combine_kernel<<<M / 2, 256>>>();

    // fork: lse fix-up parallel to out-proj
    cudaEventRecord(e3, 0);
    cudaStreamWaitEvent(s2, e3, 0);
    lse_fix_kernel<<<BH * LQ / 2, 256, 0, s2>>>(attn);
    cudaEventRecord(e4, s2);

    gemm_bias128_kernel<<<dim3(M / 128, DMODEL / 128), 256>>>(gotmp, Wo, bo, out,
                                                              M, QKV_N, DMODEL);
    cudaStreamWaitEvent(0, e4, 0);
}

// round 15
// speedup vs baseline: 1.0088x; 1.0088x over previous
#include <cuda_runtime.h>
#include <math.h>

#define BATCH 4
#define LQ 2048
#define LK 2048
#define DMODEL 512
#define NH 2
#define DK 64
#define DV 64
#define QKV_N 128

#define BQ 128
#define BK 128

// unpadded smem layout (floats)
#define OFF_Q 0
#define OFF_K0 8192
#define OFF_K1 16384
#define OFF_V0 24576
#define OFF_V1 32768
#define OFF_S 40960
#define OFF_RL 57344
#define OFF_MSK 57472      // double-buffered mask: 2 x 128
#define SMEM_FLOATS 57728
#define SMEM_BYTES (SMEM_FLOATS * 4)

typedef unsigned long long ull;

__device__ __forceinline__ ull pk2(float x, float y)
{ ull r; asm("mov.b64 %0,{%1,%2};" : "=l"(r) : "f"(x), "f"(y)); return r; }
__device__ __forceinline__ ull bc2(float x) { return pk2(x, x); }
__device__ __forceinline__ void fma2(ull& d, ull a, ull b)
{ asm("fma.rn.f32x2 %0,%1,%2,%0;" : "+l"(d) : "l"(a), "l"(b)); }
__device__ __forceinline__ float2 up2(ull v)
{ float2 r; asm("mov.b64 {%0,%1},%2;" : "=f"(r.x), "=f"(r.y) : "l"(v)); return r; }

__device__ __forceinline__ unsigned smem_u32(const void* p)
{
    unsigned a;
    asm("{ .reg .u64 t; cvta.to.shared.u64 t, %1; cvt.u32.u64 %0, t; }"
        : "=r"(a) : "l"(p));
    return a;
}
__device__ __forceinline__ void cp_async16(unsigned dst, const void* src)
{ asm volatile("cp.async.cg.shared.global [%0],[%1],16;" :: "r"(dst), "l"(src)); }
__device__ __forceinline__ void cp_commit()
{ asm volatile("cp.async.commit_group;"); }
__device__ __forceinline__ void cp_wait0()
{ asm volatile("cp.async.wait_group 0;"); }

__device__ __forceinline__ void st_cs4(float* p, float4 v)
{ asm volatile("st.global.cs.v4.f32 [%0],{%1,%2,%3,%4};"
               :: "l"(p), "f"(v.x), "f"(v.y), "f"(v.z), "f"(v.w) : "memory"); }
__device__ __forceinline__ float4 ld_cs4(const float* p)
{
    float4 v;
    asm volatile("ld.global.cs.v4.f32 {%0,%1,%2,%3},[%4];"
                 : "=f"(v.x), "=f"(v.y), "=f"(v.z), "=f"(v.w) : "l"(p));
    return v;
}

__device__ __forceinline__ int s_off(int kc, int g)
{ return OFF_S + kc * BQ + (((g + kc + (kc >> 3)) & 31) << 2); }

// 10*tanh(0.125*x) = 10 - 20/(exp(0.25x)+1); exact at +/-inf
__device__ __forceinline__ float tanh10s(float x)
{
    float e = __expf(0.25f * x);
    float r;
    asm("rcp.approx.f32 %0,%1;" : "=f"(r) : "f"(e + 1.f));
    return fmaf(-20.f, r, 10.f);
}

__device__ float g_qT[BATCH * QKV_N * LQ];
__device__ float g_kT[BATCH * QKV_N * LK];
__device__ float g_v[BATCH * LK * QKV_N];
__device__ float g_otmp[BATCH * LQ * QKV_N];   // raw SV (no lse correction)
__device__ float g_vsum[BATCH * QKV_N];
__device__ float g_wv[BATCH * NH * DMODEL];    // wv[b][h][n] = vsum_h . Wo[:,n]
__device__ float g_lse[BATCH * NH * LQ];
__device__ int g_mask_mode;  // 0=u8, 1=i32, 2=f32

__device__ __forceinline__ float mask_at(const void* p, int mode, size_t gi)
{
    if (mode == 1) return ((const int*)p)[gi] != 0 ? 1.f : 0.f;
    if (mode == 0) return ((const unsigned char*)p)[gi] != 0 ? 1.f : 0.f;
    return ((const float*)p)[gi] != 0.f ? 1.f : 0.f;
}

__global__ void detect_mask_kernel(const unsigned int* __restrict__ w)
{
    __shared__ int s_f32, s_all01;
    if (threadIdx.x == 0) { s_f32 = 0; s_all01 = 1; }
    __syncthreads();
    int f = 0, bad = 0;
    for (int i = threadIdx.x; i < 2048; i += blockDim.x) {
        unsigned v = w[i];
        if (v == 0x3F800000u) f = 1;
        if (v > 1u) bad = 1;
    }
    if (f) atomicOr(&s_f32, 1);
    if (bad) atomicExch(&s_all01, 0);
    __syncthreads();
    if (threadIdx.x == 0) g_mask_mode = s_f32 ? 2 : (s_all01 ? 1 : 0);
}

// ---- fused QKV projection: 64x128 tile, 128 threads, 8x8 frags.
__global__ __launch_bounds__(128) void gemm_qkv_kernel(
    const float* __restrict__ X0, const float* __restrict__ X1, const float* __restrict__ X2,
    const float* __restrict__ W0, const float* __restrict__ W1, const float* __restrict__ W2,
    const float* __restrict__ B0, const float* __restrict__ B1, const float* __restrict__ B2,
    float* __restrict__ Y0, float* __restrict__ Y1, float* __restrict__ Y2)
{
    __shared__ float xs[32 * 68];
    __shared__ float ws[32 * 132];
    int sel = blockIdx.y;
    const float* X = sel == 0 ? X0 : (sel == 1 ? X1 : X2);
    const float* W = sel == 0 ? W0 : (sel == 1 ? W1 : W2);
    const float* bias = sel == 0 ? B0 : (sel == 1 ? B1 : B2);
    float* Y = sel == 0 ? Y0 : (sel == 1 ? Y1 : Y2);

    int tid = threadIdx.x;
    int tx = tid & 15, ty = tid >> 4;
    int bm = blockIdx.x * 64;
    int row0 = ty * 8, col0 = tx * 8;

    ull acc2[4][8];
#pragma unroll
    for (int p = 0; p < 4; p++)
#pragma unroll
        for (int j = 0; j < 8; j++) acc2[p][j] = 0ull;

    for (int k0 = 0; k0 < DMODEL; k0 += 32) {
#pragma unroll
        for (int i = 0; i < 4; i++) {
            int linear = tid + i * 128;
            int m = linear >> 3;
            int g = (linear & 7) * 4;
            float4 v = *(const float4*)&X[(size_t)(bm + m) * DMODEL + k0 + g];
            xs[(g + 0) * 68 + m] = v.x;
            xs[(g + 1) * 68 + m] = v.y;
            xs[(g + 2) * 68 + m] = v.z;
            xs[(g + 3) * 68 + m] = v.w;
        }
#pragma unroll
        for (int i = 0; i < 8; i++) {
            int linear = tid + i * 128;
            int k = linear >> 5;
            int g = (linear & 31) * 4;
            *(float4*)&ws[k * 132 + g] = *(const float4*)&W[(size_t)(k0 + k) * QKV_N + g];
        }
        __syncthreads();
#pragma unroll
        for (int k = 0; k < 32; k++) {
            float4 xa = *(const float4*)&xs[k * 68 + row0];
            float4 xb = *(const float4*)&xs[k * 68 + row0 + 4];
            float4 wa = *(const float4*)&ws[k * 132 + col0];
            float4 wb = *(const float4*)&ws[k * 132 + col0 + 4];
            ull xp[4] = {pk2(xa.x, xa.y), pk2(xa.z, xa.w),
                         pk2(xb.x, xb.y), pk2(xb.z, xb.w)};
            ull wn[8] = {bc2(wa.x), bc2(wa.y), bc2(wa.z), bc2(wa.w),
                         bc2(wb.x), bc2(wb.y), bc2(wb.z), bc2(wb.w)};
#pragma unroll
            for (int p = 0; p < 4; p++)
#pragma unroll
                for (int j = 0; j < 8; j++)
                    fma2(acc2[p][j], xp[p], wn[j]);
        }
        __syncthreads();
    }
    float bb[8];
#pragma unroll
    for (int j = 0; j < 8; j++) bb[j] = bias[col0 + j];

    if (sel == 2) {
#pragma unroll
        for (int p = 0; p < 4; p++) {
            float r0[8], r1[8];
#pragma unroll
            for (int j = 0; j < 8; j++) {
                float2 t = up2(acc2[p][j]);
                r0[j] = t.x + bb[j];
                r1[j] = t.y + bb[j];
            }
            float* y0 = &Y[(size_t)(bm + row0 + 2 * p) * QKV_N + col0];
            *(float4*)y0 = make_float4(r0[0], r0[1], r0[2], r0[3]);
            *(float4*)(y0 + 4) = make_float4(r0[4], r0[5], r0[6], r0[7]);
            float* y1 = y0 + QKV_N;
            *(float4*)y1 = make_float4(r1[0], r1[1], r1[2], r1[3]);
            *(float4*)(y1 + 4) = make_float4(r1[4], r1[5], r1[6], r1[7]);
        }
    } else {
        int b = bm >> 11;
        int l0 = (bm & 2047) + row0;
#pragma unroll
        for (int j = 0; j < 8; j++) {
            float v[8];
#pragma unroll
            for (int p = 0; p < 4; p++) {
                float2 t = up2(acc2[p][j]);
                v[2 * p] = t.x + bb[j];
                v[2 * p + 1] = t.y + bb[j];
            }
            float* yp = &Y[((size_t)(b * QKV_N + col0 + j)) * LQ + l0];
            *(float4*)yp = make_float4(v[0], v[1], v[2], v[3]);
            *(float4*)(yp + 4) = make_float4(v[4], v[5], v[6], v[7]);
        }
    }
}

// ---- out-proj GEMM, 128x128 tile, with lse/wv epilogue:
// out = SV@Wo + bo - lse0*wv0 - lse1*wv1
__global__ __launch_bounds__(256) void gemm_out_kernel(
    const float* __restrict__ X, const float* __restrict__ W,
    const float* __restrict__ bias, float* __restrict__ Y,
    int M, int K, int N)
{
    __shared__ float xs[32 * 132];
    __shared__ float ws[32 * 132];
    int tid = threadIdx.x;
    int tx = tid & 15, ty = tid >> 4;
    int bm = blockIdx.x * 128, bn = blockIdx.y * 128;
    int row0 = ty * 8, col0 = tx * 8;

    ull acc2[4][8];
#pragma unroll
    for (int p = 0; p < 4; p++)
#pragma unroll
        for (int j = 0; j < 8; j++) acc2[p][j] = 0ull;

    for (int k0 = 0; k0 < K; k0 += 32) {
#pragma unroll
        for (int i = 0; i < 4; i++) {
            int linear = tid + i * 256;
            int m = linear >> 3;
            int g = (linear & 7) * 4;
            float4 v = *(const float4*)&X[(size_t)(bm + m) * K + k0 + g];
            xs[(g + 0) * 132 + m] = v.x;
            xs[(g + 1) * 132 + m] = v.y;
            xs[(g + 2) * 132 + m] = v.z;
            xs[(g + 3) * 132 + m] = v.w;
        }
#pragma unroll
        for (int i = 0; i < 4; i++) {
            int linear = tid + i * 256;
            int k = linear >> 5;
            int g = (linear & 31) * 4;
            *(float4*)&ws[k * 132 + g] = *(const float4*)&W[(size_t)(k0 + k) * N + bn + g];
        }
        __syncthreads();
#pragma unroll
        for (int k = 0; k < 32; k++) {
            float4 xa = *(const float4*)&xs[k * 132 + row0];
            float4 xb = *(const float4*)&xs[k * 132 + row0 + 4];
            float4 wa = *(const float4*)&ws[k * 132 + col0];
            float4 wb = *(const float4*)&ws[k * 132 + col0 + 4];
            ull xp[4] = {pk2(xa.x, xa.y), pk2(xa.z, xa.w),
                         pk2(xb.x, xb.y), pk2(xb.z, xb.w)};
            ull wn[8] = {bc2(wa.x), bc2(wa.y), bc2(wa.z), bc2(wa.w),
                         bc2(wb.x), bc2(wb.y), bc2(wb.z), bc2(wb.w)};
#pragma unroll
            for (int p = 0; p < 4; p++)
#pragma unroll
                for (int j = 0; j < 8; j++)
                    fma2(acc2[p][j], xp[p], wn[j]);
        }
        __syncthreads();
    }
    float bb[8];
#pragma unroll
    for (int j = 0; j < 8; j++) bb[j] = bias[bn + col0 + j];

    int b = bm >> 11;
    float w0[8], w1[8];
    {
        const float* wv0 = &g_wv[(b * NH + 0) * DMODEL + bn + col0];
        const float* wv1 = &g_wv[(b * NH + 1) * DMODEL + bn + col0];
#pragma unroll
        for (int j = 0; j < 8; j++) { w0[j] = wv0[j]; w1[j] = wv1[j]; }
    }
    const float* lse0 = &g_lse[(b * NH + 0) * LQ];
    const float* lse1 = &g_lse[(b * NH + 1) * LQ];
    int qbase = (bm & 2047) + row0;

#pragma unroll
    for (int p = 0; p < 4; p++) {
        int qa = qbase + 2 * p, qb = qa + 1;
        float la0 = lse0[qa], la1 = lse1[qa];
        float lb0 = lse0[qb], lb1 = lse1[qb];
        float r0[8], r1[8];
#pragma unroll
        for (int j = 0; j < 8; j++) {
            float2 t = up2(acc2[p][j]);
            r0[j] = t.x + bb[j] - la0 * w0[j] - la1 * w1[j];
            r1[j] = t.y + bb[j] - lb0 * w0[j] - lb1 * w1[j];
        }
        float* y0 = &Y[(size_t)(bm + row0 + 2 * p) * N + bn + col0];
        *(float4*)y0 = make_float4(r0[0], r0[1], r0[2], r0[3]);
        *(float4*)(y0 + 4) = make_float4(r0[4], r0[5], r0[6], r0[7]);
        float* y1 = y0 + N;
        *(float4*)y1 = make_float4(r1[0], r1[1], r1[2], r1[3]);
        *(float4*)(y1 + 4) = make_float4(r1[4], r1[5], r1[6], r1[7]);
    }
}

__global__ void vsum_zero_kernel() { g_vsum[threadIdx.x] = 0.f; }

__global__ __launch_bounds__(256) void vsum_kernel()
{
    __shared__ float red[8][128];
    int b = blockIdx.x, part = blockIdx.y;
    int c4 = (threadIdx.x & 31) * 4;
    int r0 = threadIdx.x >> 5;
    const float* base = g_v + ((size_t)b * LK + part * 128) * QKV_N;
    float4 s = make_float4(0.f, 0.f, 0.f, 0.f);
#pragma unroll 4
    for (int r = r0; r < 128; r += 8) {
        float4 v = *(const float4*)&base[(size_t)r * QKV_N + c4];
        s.x += v.x; s.y += v.y; s.z += v.z; s.w += v.w;
    }
    *(float4*)&red[r0][c4] = s;
    __syncthreads();
    if (threadIdx.x < 128) {
        float t = 0.f;
#pragma unroll
        for (int i = 0; i < 8; i++) t += red[i][threadIdx.x];
        atomicAdd(&g_vsum[b * QKV_N + threadIdx.x], t);
    }
}

// wv[b][h][n] = sum_dv vsum[b][h*64+dv] * Wo[(h*64+dv)*DMODEL + n]
__global__ __launch_bounds__(256) void wv_kernel(const float* __restrict__ Wo)
{
    __shared__ float vs[128];
    int b = blockIdx.x, n0 = blockIdx.y * 128;
    if (threadIdx.x < 128) vs[threadIdx.x] = g_vsum[b * QKV_N + threadIdx.x];
    __syncthreads();
    int h = threadIdx.x >> 7;
    int n = threadIdx.x & 127;
    float s = 0.f;
#pragma unroll 8
    for (int dv = 0; dv < 64; dv++)
        s += vs[h * 64 + dv] * Wo[(size_t)(h * 64 + dv) * DMODEL + n0 + n];
    g_wv[(b * NH + h) * DMODEL + n0 + n] = s;
}

// streaming lse fix-up: attn[row][*] -= lse[row]
__global__ __launch_bounds__(256) void lse_fix_kernel(float* __restrict__ attn)
{
    int row = blockIdx.x * 2 + (threadIdx.x >> 7);
    int lane = threadIdx.x & 127;
    float l = g_lse[row];
    float* p = attn + (size_t)row * LK;
#pragma unroll
    for (int j = 0; j < 4; j++) {
        float* q = p + (lane + j * 128) * 4;
        float4 a = ld_cs4(q);
        a.x -= l; a.y -= l; a.z -= l; a.w -= l;
        st_cs4(q, a);
    }
}

// one block = 128 queries for one (b,h); double-buffered cp.async K/V pipeline
__global__ __launch_bounds__(256) void mab_main_kernel(
    const void* __restrict__ maskp, float* __restrict__ attn)
{
    extern __shared__ float sm[];
    int tid = threadIdx.x;
    int tx = tid & 15, ty = tid >> 4;
    int m0 = ty * 8;
    int nk = tx * 8;
    int nv = tx * 4;
    int q0 = blockIdx.x * BQ;
    int h = blockIdx.y, b = blockIdx.z;
    int mode = g_mask_mode;

    const float* qtbase = g_qT + ((size_t)(b * QKV_N + h * DK)) * LQ + q0;
    const float* ktbase = g_kT + ((size_t)(b * QKV_N + h * DK)) * LK;
    const float* vbase  = g_v + (size_t)b * LK * QKV_N + h * DK;
    float* arow = attn + ((size_t)((b * NH + h) * LQ + q0)) * LK;

#pragma unroll
    for (int i = 0; i < 8; i++) {
        int lin = tid + i * 256;
        int d = lin >> 5, qq = (lin & 31) * 4;
        cp_async16(smem_u32(&sm[OFF_Q + d * 128 + qq]), &qtbase[(size_t)d * LQ + qq]);
    }
#pragma unroll
    for (int i = 0; i < 8; i++) {
        int lin = tid + i * 256;
        int d = lin >> 5, kk = (lin & 31) * 4;
        cp_async16(smem_u32(&sm[OFF_K0 + d * 128 + kk]), &ktbase[(size_t)d * LK + kk]);
    }
#pragma unroll
    for (int i = 0; i < 8; i++) {
        int lin = tid + i * 256;
        int kr = lin >> 4, dv = (lin & 15) * 4;
        cp_async16(smem_u32(&sm[OFF_V0 + kr * DV + dv]), &vbase[(size_t)kr * QKV_N + dv]);
    }
    cp_commit();
    float mreg = 0.f;
    if (tid < BK) mreg = mask_at(maskp, mode, (size_t)b * LK + tid);
    if (tid < BQ) sm[OFF_RL + tid] = 0.f;

    ull sv2[4][4];
#pragma unroll
    for (int i = 0; i < 4; i++)
#pragma unroll
        for (int j = 0; j < 4; j++) sv2[i][j] = 0ull;

    for (int c = 0; c < LK / BK; c++) {
        int k0 = c * BK;
        int kbuf = (c & 1) ? OFF_K1 : OFF_K0;
        int vbuf = (c & 1) ? OFF_V1 : OFF_V0;
        int mbuf = OFF_MSK + (c & 1) * 128;
        if (tid < BK) sm[mbuf + tid] = mreg;
        cp_wait0();
        __syncthreads();   // B: data visible; prev phases done

        if (c < 15) {
            int k1 = k0 + BK;
            int kb2 = (c & 1) ? OFF_K0 : OFF_K1;
            int vb2 = (c & 1) ? OFF_V0 : OFF_V1;
#pragma unroll
            for (int i = 0; i < 8; i++) {
                int lin = tid + i * 256;
                int d = lin >> 5, kk = (lin & 31) * 4;
                cp_async16(smem_u32(&sm[kb2 + d * 128 + kk]),
                           &ktbase[(size_t)d * LK + k1 + kk]);
            }
#pragma unroll
            for (int i = 0; i < 8; i++) {
                int lin = tid + i * 256;
                int kr = lin >> 4, dv = (lin & 15) * 4;
                cp_async16(smem_u32(&sm[vb2 + kr * DV + dv]),
                           &vbase[(size_t)(k1 + kr) * QKV_N + dv]);
            }
            cp_commit();
            if (tid < BK) mreg = mask_at(maskp, mode, (size_t)b * LK + k1 + tid);
        }

        // phase 1: S = q @ k^T
        ull acc2[4][8];
#pragma unroll
        for (int p = 0; p < 4; p++)
#pragma unroll
            for (int j = 0; j < 8; j++) acc2[p][j] = 0ull;

#pragma unroll 4
        for (int d = 0; d < DK; d++) {
            float4 qa = *(const float4*)&sm[OFF_Q + d * 128 + m0];
            float4 qb = *(const float4*)&sm[OFF_Q + d * 128 + m0 + 4];
            float4 ka = *(const float4*)&sm[kbuf + d * 128 + nk];
            float4 kb4 = *(const float4*)&sm[kbuf + d * 128 + nk + 4];
            ull qp[4] = {pk2(qa.x, qa.y), pk2(qa.z, qa.w),
                         pk2(qb.x, qb.y), pk2(qb.z, qb.w)};
            ull kb[8] = {bc2(ka.x), bc2(ka.y), bc2(ka.z), bc2(ka.w),
                         bc2(kb4.x), bc2(kb4.y), bc2(kb4.z), bc2(kb4.w)};
#pragma unroll
            for (int p = 0; p < 4; p++)
#pragma unroll
                for (int j = 0; j < 8; j++)
                    fma2(acc2[p][j], qp[p], kb[j]);
        }

        float acc[8][8];
#pragma unroll
        for (int p = 0; p < 4; p++)
#pragma unroll
            for (int j = 0; j < 8; j++) {
                float2 v = up2(acc2[p][j]);
                acc[2 * p][j] = v.x;
                acc[2 * p + 1][j] = v.y;
            }

        float mk[8];
#pragma unroll
        for (int j = 0; j < 8; j++) mk[j] = sm[mbuf + nk + j];

        float er[8];
#pragma unroll
        for (int i = 0; i < 8; i++) {
            float rs = 0.f;
#pragma unroll
            for (int j = 0; j < 8; j++) {
                float s = tanh10s(acc[i][j]);
                if (mk[j] != 0.f) s = -10.f;
                acc[i][j] = s;
                rs += __expf(s);
            }
            er[i] = rs;
            float* ap = &arow[(size_t)(m0 + i) * LK + k0 + nk];
            st_cs4(ap, make_float4(acc[i][0], acc[i][1], acc[i][2], acc[i][3]));
            st_cs4(ap + 4, make_float4(acc[i][4], acc[i][5], acc[i][6], acc[i][7]));
        }
#pragma unroll
        for (int d = 1; d < 16; d <<= 1) {
#pragma unroll
            for (int i = 0; i < 8; i++)
                er[i] += __shfl_xor_sync(0xffffffffu, er[i], d);
        }
        if (tx == 0) {
#pragma unroll
            for (int i = 0; i < 8; i++)
                sm[OFF_RL + m0 + i] += er[i];
        }
        {
            int g = m0 >> 2;
#pragma unroll
            for (int j = 0; j < 8; j++) {
                int kc = nk + j;
                *(float4*)&sm[s_off(kc, g)] =
                    make_float4(acc[0][j], acc[1][j], acc[2][j], acc[3][j]);
                *(float4*)&sm[s_off(kc, g + 1)] =
                    make_float4(acc[4][j], acc[5][j], acc[6][j], acc[7][j]);
            }
        }
        __syncthreads();   // C: S visible

        // phase 2: SV += S_chunk @ v_chunk
        {
            int g = m0 >> 2;
#pragma unroll 8
            for (int kc = 0; kc < BK; kc++) {
                float4 sa = *(const float4*)&sm[s_off(kc, g)];
                float4 sb = *(const float4*)&sm[s_off(kc, g + 1)];
                float4 vv = *(const float4*)&sm[vbuf + kc * DV + nv];
                ull sp[4] = {pk2(sa.x, sa.y), pk2(sa.z, sa.w),
                             pk2(sb.x, sb.y), pk2(sb.z, sb.w)};
                ull vb[4] = {bc2(vv.x), bc2(vv.y), bc2(vv.z), bc2(vv.w)};
#pragma unroll
                for (int p = 0; p < 4; p++)
#pragma unroll
                    for (int j = 0; j < 4; j++)
                        fma2(sv2[p][j], sp[p], vb[j]);
            }
        }
    }

    __syncthreads();
    if (tid < BQ)
        g_lse[(b * NH + h) * LQ + q0 + tid] = logf(sm[OFF_RL + tid]);

    {   // store raw SV (vsum/lse correction folded into out-proj epilogue)
#pragma unroll
        for (int p = 0; p < 4; p++) {
            float2 c0 = up2(sv2[p][0]), c1 = up2(sv2[p][1]);
            float2 c2 = up2(sv2[p][2]), c3 = up2(sv2[p][3]);
            size_t r0 = ((size_t)b * LQ + q0 + m0 + 2 * p) * QKV_N + h * DK + nv;
            *(float4*)&g_otmp[r0] = make_float4(c0.x, c1.x, c2.x, c3.x);
            *(float4*)&g_otmp[r0 + QKV_N] = make_float4(c0.y, c1.y, c2.y, c3.y);
        }
    }
}

extern "C" void kernel_launch(void* const* d_in, const int* in_sizes, int n_in,
                              void* d_out, int out_size)
{
    const float* Q  = (const float*)d_in[0];
    const float* K  = (const float*)d_in[1];
    const float* V  = (const float*)d_in[2];
    const void*  Mk = d_in[3];
    const float* Wq = (const float*)d_in[4];
    const float* bq = (const float*)d_in[5];
    const float* Wk = (const float*)d_in[6];
    const float* bk = (const float*)d_in[7];
    const float* Wv = (const float*)d_in[8];
    const float* bv = (const float*)d_in[9];
    const float* Wo = (const float*)d_in[10];
    const float* bo = (const float*)d_in[11];

    float* out  = (float*)d_out;
    float* attn = out + (size_t)BATCH * LQ * DMODEL;

    float *gqt, *gkt, *gv, *gotmp;
    cudaGetSymbolAddress((void**)&gqt, g_qT);
    cudaGetSymbolAddress((void**)&gkt, g_kT);
    cudaGetSymbolAddress((void**)&gv, g_v);
    cudaGetSymbolAddress((void**)&gotmp, g_otmp);

    static int inited = 0;
    static cudaStream_t s2;
    static cudaEvent_t eD, e1, e2, e3, e4;
    if (!inited) {
        cudaFuncSetAttribute(mab_main_kernel,
                             cudaFuncAttributeMaxDynamicSharedMemorySize, SMEM_BYTES);
        cudaStreamCreateWithFlags(&s2, cudaStreamNonBlocking);
        cudaEventCreateWithFlags(&eD, cudaEventDisableTiming);
        cudaEventCreateWithFlags(&e1, cudaEventDisableTiming);
        cudaEventCreateWithFlags(&e2, cudaEventDisableTiming);
        cudaEventCreateWithFlags(&e3, cudaEventDisableTiming);
        cudaEventCreateWithFlags(&e4, cudaEventDisableTiming);
        inited = 1;
    }

    const int M = BATCH * LQ;  // 8192

    // detect_mask on side stream, parallel with QKV (only main consumes it)
    cudaEventRecord(eD, 0);
    cudaStreamWaitEvent(s2, eD, 0);
    detect_mask_kernel<<<1, 256, 0, s2>>>((const unsigned int*)Mk);

    gemm_qkv_kernel<<<dim3(M / 64, 3), 128>>>(Q, K, V, Wq, Wk, Wv,
                                              bq, bk, bv, gqt, gkt, gv);

    // vsum + wv on side stream, fully parallel with main (joined before out-proj)
    cudaEventRecord(e1, 0);
    cudaStreamWaitEvent(s2, e1, 0);
    vsum_zero_kernel<<<1, BATCH * QKV_N, 0, s2>>>();
    vsum_kernel<<<dim3(BATCH, 16), 256, 0, s2>>>();
    wv_kernel<<<dim3(BATCH, DMODEL / 128), 256, 0, s2>>>(Wo);
    cudaEventRecord(e2, s2);

    // main waits for detect_mask (via s2 ordering through e2? no: explicit)
    cudaStreamWaitEvent(0, e2, 0);  // conservative: also covers detect_mask (same stream, earlier)
    mab_main_kernel<<<dim3(LQ / BQ, NH, BATCH), 256, SMEM_BYTES>>>(Mk, attn);

    // fork: lse fix-up parallel with out-proj
    cudaEventRecord(e3, 0);
    cudaStreamWaitEvent(s2, e3, 0);
    lse_fix_kernel<<<BATCH * NH * LQ / 2, 256, 0, s2>>>(attn);
    cudaEventRecord(e4, s2);

    gemm_out_kernel<<<dim3(M / 128, DMODEL / 128), 256>>>(gotmp, Wo, bo, out,
                                                          M, QKV_N, DMODEL);
    cudaStreamWaitEvent(0, e4, 0);
}

// round 16
// speedup vs baseline: 1.0463x; 1.0372x over previous
#include <cuda_runtime.h>
#include <math.h>

#define BATCH 4
#define LQ 2048
#define LK 2048
#define DMODEL 512
#define NH 2
#define DK 64
#define DV 64
#define QKV_N 128

#define BQ 128
#define BK 128

// unpadded smem layout (floats)
#define OFF_Q 0
#define OFF_K0 8192
#define OFF_K1 16384
#define OFF_V0 24576
#define OFF_V1 32768
#define OFF_S 40960
#define OFF_RL 57344
#define OFF_MSK 57472      // double-buffered mask: 2 x 128
#define SMEM_FLOATS 57728
#define SMEM_BYTES (SMEM_FLOATS * 4)

typedef unsigned long long ull;

__device__ __forceinline__ ull pk2(float x, float y)
{ ull r; asm("mov.b64 %0,{%1,%2};" : "=l"(r) : "f"(x), "f"(y)); return r; }
__device__ __forceinline__ ull bc2(float x) { return pk2(x, x); }
__device__ __forceinline__ void fma2(ull& d, ull a, ull b)
{ asm("fma.rn.f32x2 %0,%1,%2,%0;" : "+l"(d) : "l"(a), "l"(b)); }
__device__ __forceinline__ float2 up2(ull v)
{ float2 r; asm("mov.b64 {%0,%1},%2;" : "=f"(r.x), "=f"(r.y) : "l"(v)); return r; }

__device__ __forceinline__ unsigned smem_u32(const void* p)
{
    unsigned a;
    asm("{ .reg .u64 t; cvta.to.shared.u64 t, %1; cvt.u32.u64 %0, t; }"
        : "=r"(a) : "l"(p));
    return a;
}
__device__ __forceinline__ void cp_async16(unsigned dst, const void* src)
{ asm volatile("cp.async.cg.shared.global [%0],[%1],16;" :: "r"(dst), "l"(src)); }
__device__ __forceinline__ void cp_commit()
{ asm volatile("cp.async.commit_group;"); }
__device__ __forceinline__ void cp_wait0()
{ asm volatile("cp.async.wait_group 0;"); }

__device__ __forceinline__ void st_cs4(float* p, float4 v)
{ asm volatile("st.global.cs.v4.f32 [%0],{%1,%2,%3,%4};"
               :: "l"(p), "f"(v.x), "f"(v.y), "f"(v.z), "f"(v.w) : "memory"); }
__device__ __forceinline__ float4 ld_cs4(const float* p)
{
    float4 v;
    asm volatile("ld.global.cs.v4.f32 {%0,%1,%2,%3},[%4];"
                 : "=f"(v.x), "=f"(v.y), "=f"(v.z), "=f"(v.w) : "l"(p));
    return v;
}

__device__ __forceinline__ int s_off(int kc, int g)
{ return OFF_S + kc * BQ + (((g + kc + (kc >> 3)) & 31) << 2); }

// 10*tanh(0.125*x) = 10 - 20/(exp(0.25x)+1); exact at +/-inf
__device__ __forceinline__ float tanh10s(float x)
{
    float e = __expf(0.25f * x);
    float r;
    asm("rcp.approx.f32 %0,%1;" : "=f"(r) : "f"(e + 1.f));
    return fmaf(-20.f, r, 10.f);
}

__device__ float g_qT[BATCH * QKV_N * LQ];
__device__ float g_kT[BATCH * QKV_N * LK];
__device__ float g_v[BATCH * LK * QKV_N];
__device__ float g_otmp[BATCH * LQ * QKV_N];   // raw SV
__device__ float g_vsum[BATCH * QKV_N];
__device__ float g_wv[BATCH * NH * DMODEL];    // wv[b][h][n] = vsum_h . Wo[:,n]
__device__ float g_lse[BATCH * NH * LQ];
__device__ int g_mask_mode;  // 0=u8, 1=i32, 2=f32

__device__ __forceinline__ float mask_at(const void* p, int mode, size_t gi)
{
    if (mode == 1) return ((const int*)p)[gi] != 0 ? 1.f : 0.f;
    if (mode == 0) return ((const unsigned char*)p)[gi] != 0 ? 1.f : 0.f;
    return ((const float*)p)[gi] != 0.f ? 1.f : 0.f;
}

__global__ void detect_mask_kernel(const unsigned int* __restrict__ w)
{
    __shared__ int s_f32, s_all01;
    if (threadIdx.x == 0) { s_f32 = 0; s_all01 = 1; }
    __syncthreads();
    int f = 0, bad = 0;
    for (int i = threadIdx.x; i < 2048; i += blockDim.x) {
        unsigned v = w[i];
        if (v == 0x3F800000u) f = 1;
        if (v > 1u) bad = 1;
    }
    if (f) atomicOr(&s_f32, 1);
    if (bad) atomicExch(&s_all01, 0);
    __syncthreads();
    if (threadIdx.x == 0) g_mask_mode = s_f32 ? 2 : (s_all01 ? 1 : 0);
}

// ---- fused QKV projection: 64x128 tile, 128 threads, 8x8 frags.
__global__ __launch_bounds__(128) void gemm_qkv_kernel(
    const float* __restrict__ X0, const float* __restrict__ X1, const float* __restrict__ X2,
    const float* __restrict__ W0, const float* __restrict__ W1, const float* __restrict__ W2,
    const float* __restrict__ B0, const float* __restrict__ B1, const float* __restrict__ B2,
    float* __restrict__ Y0, float* __restrict__ Y1, float* __restrict__ Y2)
{
    __shared__ float xs[32 * 68];
    __shared__ float ws[32 * 132];
    int sel = blockIdx.y;
    const float* X = sel == 0 ? X0 : (sel == 1 ? X1 : X2);
    const float* W = sel == 0 ? W0 : (sel == 1 ? W1 : W2);
    const float* bias = sel == 0 ? B0 : (sel == 1 ? B1 : B2);
    float* Y = sel == 0 ? Y0 : (sel == 1 ? Y1 : Y2);

    int tid = threadIdx.x;
    int tx = tid & 15, ty = tid >> 4;
    int bm = blockIdx.x * 64;
    int row0 = ty * 8, col0 = tx * 8;

    ull acc2[4][8];
#pragma unroll
    for (int p = 0; p < 4; p++)
#pragma unroll
        for (int j = 0; j < 8; j++) acc2[p][j] = 0ull;

    for (int k0 = 0; k0 < DMODEL; k0 += 32) {
#pragma unroll
        for (int i = 0; i < 4; i++) {
            int linear = tid + i * 128;
            int m = linear >> 3;
            int g = (linear & 7) * 4;
            float4 v = *(const float4*)&X[(size_t)(bm + m) * DMODEL + k0 + g];
            xs[(g + 0) * 68 + m] = v.x;
            xs[(g + 1) * 68 + m] = v.y;
            xs[(g + 2) * 68 + m] = v.z;
            xs[(g + 3) * 68 + m] = v.w;
        }
#pragma unroll
        for (int i = 0; i < 8; i++) {
            int linear = tid + i * 128;
            int k = linear >> 5;
            int g = (linear & 31) * 4;
            *(float4*)&ws[k * 132 + g] = *(const float4*)&W[(size_t)(k0 + k) * QKV_N + g];
        }
        __syncthreads();
#pragma unroll
        for (int k = 0; k < 32; k++) {
            float4 xa = *(const float4*)&xs[k * 68 + row0];
            float4 xb = *(const float4*)&xs[k * 68 + row0 + 4];
            float4 wa = *(const float4*)&ws[k * 132 + col0];
            float4 wb = *(const float4*)&ws[k * 132 + col0 + 4];
            ull xp[4] = {pk2(xa.x, xa.y), pk2(xa.z, xa.w),
                         pk2(xb.x, xb.y), pk2(xb.z, xb.w)};
            ull wn[8] = {bc2(wa.x), bc2(wa.y), bc2(wa.z), bc2(wa.w),
                         bc2(wb.x), bc2(wb.y), bc2(wb.z), bc2(wb.w)};
#pragma unroll
            for (int p = 0; p < 4; p++)
#pragma unroll
                for (int j = 0; j < 8; j++)
                    fma2(acc2[p][j], xp[p], wn[j]);
        }
        __syncthreads();
    }
    float bb[8];
#pragma unroll
    for (int j = 0; j < 8; j++) bb[j] = bias[col0 + j];

    if (sel == 2) {
#pragma unroll
        for (int p = 0; p < 4; p++) {
            float r0[8], r1[8];
#pragma unroll
            for (int j = 0; j < 8; j++) {
                float2 t = up2(acc2[p][j]);
                r0[j] = t.x + bb[j];
                r1[j] = t.y + bb[j];
            }
            float* y0 = &Y[(size_t)(bm + row0 + 2 * p) * QKV_N + col0];
            *(float4*)y0 = make_float4(r0[0], r0[1], r0[2], r0[3]);
            *(float4*)(y0 + 4) = make_float4(r0[4], r0[5], r0[6], r0[7]);
            float* y1 = y0 + QKV_N;
            *(float4*)y1 = make_float4(r1[0], r1[1], r1[2], r1[3]);
            *(float4*)(y1 + 4) = make_float4(r1[4], r1[5], r1[6], r1[7]);
        }
    } else {
        int b = bm >> 11;
        int l0 = (bm & 2047) + row0;
#pragma unroll
        for (int j = 0; j < 8; j++) {
            float v[8];
#pragma unroll
            for (int p = 0; p < 4; p++) {
                float2 t = up2(acc2[p][j]);
                v[2 * p] = t.x + bb[j];
                v[2 * p + 1] = t.y + bb[j];
            }
            float* yp = &Y[((size_t)(b * QKV_N + col0 + j)) * LQ + l0];
            *(float4*)yp = make_float4(v[0], v[1], v[2], v[3]);
            *(float4*)(yp + 4) = make_float4(v[4], v[5], v[6], v[7]);
        }
    }
}

// ---- out-proj GEMM with lse/wv epilogue: out = SV@Wo + bo - lse0*wv0 - lse1*wv1
__global__ __launch_bounds__(256) void gemm_out_kernel(
    const float* __restrict__ X, const float* __restrict__ W,
    const float* __restrict__ bias, float* __restrict__ Y,
    int M, int K, int N)
{
    __shared__ float xs[32 * 132];
    __shared__ float ws[32 * 132];
    int tid = threadIdx.x;
    int tx = tid & 15, ty = tid >> 4;
    int bm = blockIdx.x * 128, bn = blockIdx.y * 128;
    int row0 = ty * 8, col0 = tx * 8;

    ull acc2[4][8];
#pragma unroll
    for (int p = 0; p < 4; p++)
#pragma unroll
        for (int j = 0; j < 8; j++) acc2[p][j] = 0ull;

    for (int k0 = 0; k0 < K; k0 += 32) {
#pragma unroll
        for (int i = 0; i < 4; i++) {
            int linear = tid + i * 256;
            int m = linear >> 3;
            int g = (linear & 7) * 4;
            float4 v = *(const float4*)&X[(size_t)(bm + m) * K + k0 + g];
            xs[(g + 0) * 132 + m] = v.x;
            xs[(g + 1) * 132 + m] = v.y;
            xs[(g + 2) * 132 + m] = v.z;
            xs[(g + 3) * 132 + m] = v.w;
        }
#pragma unroll
        for (int i = 0; i < 4; i++) {
            int linear = tid + i * 256;
            int k = linear >> 5;
            int g = (linear & 31) * 4;
            *(float4*)&ws[k * 132 + g] = *(const float4*)&W[(size_t)(k0 + k) * N + bn + g];
        }
        __syncthreads();
#pragma unroll
        for (int k = 0; k < 32; k++) {
            float4 xa = *(const float4*)&xs[k * 132 + row0];
            float4 xb = *(const float4*)&xs[k * 132 + row0 + 4];
            float4 wa = *(const float4*)&ws[k * 132 + col0];
            float4 wb = *(const float4*)&ws[k * 132 + col0 + 4];
            ull xp[4] = {pk2(xa.x, xa.y), pk2(xa.z, xa.w),
                         pk2(xb.x, xb.y), pk2(xb.z, xb.w)};
            ull wn[8] = {bc2(wa.x), bc2(wa.y), bc2(wa.z), bc2(wa.w),
                         bc2(wb.x), bc2(wb.y), bc2(wb.z), bc2(wb.w)};
#pragma unroll
            for (int p = 0; p < 4; p++)
#pragma unroll
                for (int j = 0; j < 8; j++)
                    fma2(acc2[p][j], xp[p], wn[j]);
        }
        __syncthreads();
    }
    float bb[8];
#pragma unroll
    for (int j = 0; j < 8; j++) bb[j] = bias[bn + col0 + j];

    int b = bm >> 11;
    float w0[8], w1[8];
    {
        const float* wv0 = &g_wv[(b * NH + 0) * DMODEL + bn + col0];
        const float* wv1 = &g_wv[(b * NH + 1) * DMODEL + bn + col0];
#pragma unroll
        for (int j = 0; j < 8; j++) { w0[j] = wv0[j]; w1[j] = wv1[j]; }
    }
    const float* lse0 = &g_lse[(b * NH + 0) * LQ];
    const float* lse1 = &g_lse[(b * NH + 1) * LQ];
    int qbase = (bm & 2047) + row0;

#pragma unroll
    for (int p = 0; p < 4; p++) {
        int qa = qbase + 2 * p, qb = qa + 1;
        float la0 = lse0[qa], la1 = lse1[qa];
        float lb0 = lse0[qb], lb1 = lse1[qb];
        float r0[8], r1[8];
#pragma unroll
        for (int j = 0; j < 8; j++) {
            float2 t = up2(acc2[p][j]);
            r0[j] = t.x + bb[j] - la0 * w0[j] - la1 * w1[j];
            r1[j] = t.y + bb[j] - lb0 * w0[j] - lb1 * w1[j];
        }
        float* y0 = &Y[(size_t)(bm + row0 + 2 * p) * N + bn + col0];
        *(float4*)y0 = make_float4(r0[0], r0[1], r0[2], r0[3]);
        *(float4*)(y0 + 4) = make_float4(r0[4], r0[5], r0[6], r0[7]);
        float* y1 = y0 + N;
        *(float4*)y1 = make_float4(r1[0], r1[1], r1[2], r1[3]);
        *(float4*)(y1 + 4) = make_float4(r1[4], r1[5], r1[6], r1[7]);
    }
}

__global__ void vsum_zero_kernel() { g_vsum[threadIdx.x] = 0.f; }

__global__ __launch_bounds__(256) void vsum_kernel()
{
    __shared__ float red[8][128];
    int b = blockIdx.x, part = blockIdx.y;
    int c4 = (threadIdx.x & 31) * 4;
    int r0 = threadIdx.x >> 5;
    const float* base = g_v + ((size_t)b * LK + part * 128) * QKV_N;
    float4 s = make_float4(0.f, 0.f, 0.f, 0.f);
#pragma unroll 4
    for (int r = r0; r < 128; r += 8) {
        float4 v = *(const float4*)&base[(size_t)r * QKV_N + c4];
        s.x += v.x; s.y += v.y; s.z += v.z; s.w += v.w;
    }
    *(float4*)&red[r0][c4] = s;
    __syncthreads();
    if (threadIdx.x < 128) {
        float t = 0.f;
#pragma unroll
        for (int i = 0; i < 8; i++) t += red[i][threadIdx.x];
        atomicAdd(&g_vsum[b * QKV_N + threadIdx.x], t);
    }
}

// wv[b][h][n] = sum_dv vsum[b][h*64+dv] * Wo[(h*64+dv)*DMODEL + n]
__global__ __launch_bounds__(256) void wv_kernel(const float* __restrict__ Wo)
{
    __shared__ float vs[128];
    int b = blockIdx.x, n0 = blockIdx.y * 128;
    if (threadIdx.x < 128) vs[threadIdx.x] = g_vsum[b * QKV_N + threadIdx.x];
    __syncthreads();
    int h = threadIdx.x >> 7;
    int n = threadIdx.x & 127;
    float s = 0.f;
#pragma unroll 8
    for (int dv = 0; dv < 64; dv++)
        s += vs[h * 64 + dv] * Wo[(size_t)(h * 64 + dv) * DMODEL + n0 + n];
    g_wv[(b * NH + h) * DMODEL + n0 + n] = s;
}

// streaming lse fix-up: attn[row][*] -= lse[row]
__global__ __launch_bounds__(256) void lse_fix_kernel(float* __restrict__ attn)
{
    int row = blockIdx.x * 2 + (threadIdx.x >> 7);
    int lane = threadIdx.x & 127;
    float l = g_lse[row];
    float* p = attn + (size_t)row * LK;
#pragma unroll
    for (int j = 0; j < 4; j++) {
        float* q = p + (lane + j * 128) * 4;
        float4 a = ld_cs4(q);
        a.x -= l; a.y -= l; a.z -= l; a.w -= l;
        st_cs4(q, a);
    }
}

// one block = 128 queries for one (b,h); double-buffered cp.async K/V pipeline
__global__ __launch_bounds__(256) void mab_main_kernel(
    const void* __restrict__ maskp, float* __restrict__ attn)
{
    extern __shared__ float sm[];
    int tid = threadIdx.x;
    int tx = tid & 15, ty = tid >> 4;
    int m0 = ty * 8;
    int nk = tx * 8;
    int nv = tx * 4;
    int q0 = blockIdx.x * BQ;
    int h = blockIdx.y, b = blockIdx.z;
    int mode = g_mask_mode;

    const float* qtbase = g_qT + ((size_t)(b * QKV_N + h * DK)) * LQ + q0;
    const float* ktbase = g_kT + ((size_t)(b * QKV_N + h * DK)) * LK;
    const float* vbase  = g_v + (size_t)b * LK * QKV_N + h * DK;
    float* arow = attn + ((size_t)((b * NH + h) * LQ + q0)) * LK;

#pragma unroll
    for (int i = 0; i < 8; i++) {
        int lin = tid + i * 256;
        int d = lin >> 5, qq = (lin & 31) * 4;
        cp_async16(smem_u32(&sm[OFF_Q + d * 128 + qq]), &qtbase[(size_t)d * LQ + qq]);
    }
#pragma unroll
    for (int i = 0; i < 8; i++) {
        int lin = tid + i * 256;
        int d = lin >> 5, kk = (lin & 31) * 4;
        cp_async16(smem_u32(&sm[OFF_K0 + d * 128 + kk]), &ktbase[(size_t)d * LK + kk]);
    }
#pragma unroll
    for (int i = 0; i < 8; i++) {
        int lin = tid + i * 256;
        int kr = lin >> 4, dv = (lin & 15) * 4;
        cp_async16(smem_u32(&sm[OFF_V0 + kr * DV + dv]), &vbase[(size_t)kr * QKV_N + dv]);
    }
    cp_commit();
    float mreg = 0.f;
    if (tid < BK) mreg = mask_at(maskp, mode, (size_t)b * LK + tid);
    if (tid < BQ) sm[OFF_RL + tid] = 0.f;

    ull sv2[4][4];
#pragma unroll
    for (int i = 0; i < 4; i++)
#pragma unroll
        for (int j = 0; j < 4; j++) sv2[i][j] = 0ull;

    for (int c = 0; c < LK / BK; c++) {
        int k0 = c * BK;
        int kbuf = (c & 1) ? OFF_K1 : OFF_K0;
        int vbuf = (c & 1) ? OFF_V1 : OFF_V0;
        int mbuf = OFF_MSK + (c & 1) * 128;
        if (tid < BK) sm[mbuf + tid] = mreg;
        cp_wait0();
        __syncthreads();   // B: data visible; prev phases done

        if (c < 15) {
            int k1 = k0 + BK;
            int kb2 = (c & 1) ? OFF_K0 : OFF_K1;
            int vb2 = (c & 1) ? OFF_V0 : OFF_V1;
#pragma unroll
            for (int i = 0; i < 8; i++) {
                int lin = tid + i * 256;
                int d = lin >> 5, kk = (lin & 31) * 4;
                cp_async16(smem_u32(&sm[kb2 + d * 128 + kk]),
                           &ktbase[(size_t)d * LK + k1 + kk]);
            }
#pragma unroll
            for (int i = 0; i < 8; i++) {
                int lin = tid + i * 256;
                int kr = lin >> 4, dv = (lin & 15) * 4;
                cp_async16(smem_u32(&sm[vb2 + kr * DV + dv]),
                           &vbase[(size_t)(k1 + kr) * QKV_N + dv]);
            }
            cp_commit();
            if (tid < BK) mreg = mask_at(maskp, mode, (size_t)b * LK + k1 + tid);
        }

        // phase 1: S = q @ k^T
        ull acc2[4][8];
#pragma unroll
        for (int p = 0; p < 4; p++)
#pragma unroll
            for (int j = 0; j < 8; j++) acc2[p][j] = 0ull;

#pragma unroll 4
        for (int d = 0; d < DK; d++) {
            float4 qa = *(const float4*)&sm[OFF_Q + d * 128 + m0];
            float4 qb = *(const float4*)&sm[OFF_Q + d * 128 + m0 + 4];
            float4 ka = *(const float4*)&sm[kbuf + d * 128 + nk];
            float4 kb4 = *(const float4*)&sm[kbuf + d * 128 + nk + 4];
            ull qp[4] = {pk2(qa.x, qa.y), pk2(qa.z, qa.w),
                         pk2(qb.x, qb.y), pk2(qb.z, qb.w)};
            ull kb[8] = {bc2(ka.x), bc2(ka.y), bc2(ka.z), bc2(ka.w),
                         bc2(kb4.x), bc2(kb4.y), bc2(kb4.z), bc2(kb4.w)};
#pragma unroll
            for (int p = 0; p < 4; p++)
#pragma unroll
                for (int j = 0; j < 8; j++)
                    fma2(acc2[p][j], qp[p], kb[j]);
        }

        float acc[8][8];
#pragma unroll
        for (int p = 0; p < 4; p++)
#pragma unroll
            for (int j = 0; j < 8; j++) {
                float2 v = up2(acc2[p][j]);
                acc[2 * p][j] = v.x;
                acc[2 * p + 1][j] = v.y;
            }

        float mk[8];
#pragma unroll
        for (int j = 0; j < 8; j++) mk[j] = sm[mbuf + nk + j];

        float er[8];
#pragma unroll
        for (int i = 0; i < 8; i++) {
            float rs = 0.f;
#pragma unroll
            for (int j = 0; j < 8; j++) {
                float s = tanh10s(acc[i][j]);
                if (mk[j] != 0.f) s = -10.f;
                acc[i][j] = s;
                rs += __expf(s);
            }
            er[i] = rs;
            float* ap = &arow[(size_t)(m0 + i) * LK + k0 + nk];
            st_cs4(ap, make_float4(acc[i][0], acc[i][1], acc[i][2], acc[i][3]));
            st_cs4(ap + 4, make_float4(acc[i][4], acc[i][5], acc[i][6], acc[i][7]));
        }
#pragma unroll
        for (int d = 1; d < 16; d <<= 1) {
#pragma unroll
            for (int i = 0; i < 8; i++)
                er[i] += __shfl_xor_sync(0xffffffffu, er[i], d);
        }
        if (tx == 0) {
#pragma unroll
            for (int i = 0; i < 8; i++)
                sm[OFF_RL + m0 + i] += er[i];
        }
        {
            int g = m0 >> 2;
#pragma unroll
            for (int j = 0; j < 8; j++) {
                int kc = nk + j;
                *(float4*)&sm[s_off(kc, g)] =
                    make_float4(acc[0][j], acc[1][j], acc[2][j], acc[3][j]);
                *(float4*)&sm[s_off(kc, g + 1)] =
                    make_float4(acc[4][j], acc[5][j], acc[6][j], acc[7][j]);
            }
        }
        __syncthreads();   // C: S visible

        // phase 2: SV += S_chunk @ v_chunk
        {
            int g = m0 >> 2;
#pragma unroll 8
            for (int kc = 0; kc < BK; kc++) {
                float4 sa = *(const float4*)&sm[s_off(kc, g)];
                float4 sb = *(const float4*)&sm[s_off(kc, g + 1)];
                float4 vv = *(const float4*)&sm[vbuf + kc * DV + nv];
                ull sp[4] = {pk2(sa.x, sa.y), pk2(sa.z, sa.w),
                             pk2(sb.x, sb.y), pk2(sb.z, sb.w)};
                ull vb[4] = {bc2(vv.x), bc2(vv.y), bc2(vv.z), bc2(vv.w)};
#pragma unroll
                for (int p = 0; p < 4; p++)
#pragma unroll
                    for (int j = 0; j < 4; j++)
                        fma2(sv2[p][j], sp[p], vb[j]);
            }
        }
    }

    __syncthreads();
    if (tid < BQ)
        g_lse[(b * NH + h) * LQ + q0 + tid] = logf(sm[OFF_RL + tid]);

    {   // store raw SV (lse/vsum correction folded into out-proj epilogue)
#pragma unroll
        for (int p = 0; p < 4; p++) {
            float2 c0 = up2(sv2[p][0]), c1 = up2(sv2[p][1]);
            float2 c2 = up2(sv2[p][2]), c3 = up2(sv2[p][3]);
            size_t r0 = ((size_t)b * LQ + q0 + m0 + 2 * p) * QKV_N + h * DK + nv;
            *(float4*)&g_otmp[r0] = make_float4(c0.x, c1.x, c2.x, c3.x);
            *(float4*)&g_otmp[r0 + QKV_N] = make_float4(c0.y, c1.y, c2.y, c3.y);
        }
    }
}

extern "C" void kernel_launch(void* const* d_in, const int* in_sizes, int n_in,
                              void* d_out, int out_size)
{
    const float* Q  = (const float*)d_in[0];
    const float* K  = (const float*)d_in[1];
    const float* V  = (const float*)d_in[2];
    const void*  Mk = d_in[3];
    const float* Wq = (const float*)d_in[4];
    const float* bq = (const float*)d_in[5];
    const float* Wk = (const float*)d_in[6];
    const float* bk = (const float*)d_in[7];
    const float* Wv = (const float*)d_in[8];
    const float* bv = (const float*)d_in[9];
    const float* Wo = (const float*)d_in[10];
    const float* bo = (const float*)d_in[11];

    float* out  = (float*)d_out;
    float* attn = out + (size_t)BATCH * LQ * DMODEL;

    float *gqt, *gkt, *gv, *gotmp;
    cudaGetSymbolAddress((void**)&gqt, g_qT);
    cudaGetSymbolAddress((void**)&gkt, g_kT);
    cudaGetSymbolAddress((void**)&gv, g_v);
    cudaGetSymbolAddress((void**)&gotmp, g_otmp);

    static int inited = 0;
    static cudaStream_t s2;
    static cudaEvent_t eD, eDm, e1, e2, e3, e4;
    if (!inited) {
        cudaFuncSetAttribute(mab_main_kernel,
                             cudaFuncAttributeMaxDynamicSharedMemorySize, SMEM_BYTES);
        cudaStreamCreateWithFlags(&s2, cudaStreamNonBlocking);
        cudaEventCreateWithFlags(&eD, cudaEventDisableTiming);
        cudaEventCreateWithFlags(&eDm, cudaEventDisableTiming);
        cudaEventCreateWithFlags(&e1, cudaEventDisableTiming);
        cudaEventCreateWithFlags(&e2, cudaEventDisableTiming);
        cudaEventCreateWithFlags(&e3, cudaEventDisableTiming);
        cudaEventCreateWithFlags(&e4, cudaEventDisableTiming);
        inited = 1;
    }

    const int M = BATCH * LQ;  // 8192

    // detect_mask on side stream, parallel with QKV
    cudaEventRecord(eD, 0);
    cudaStreamWaitEvent(s2, eD, 0);
    detect_mask_kernel<<<1, 256, 0, s2>>>((const unsigned int*)Mk);
    cudaEventRecord(eDm, s2);

    gemm_qkv_kernel<<<dim3(M / 64, 3), 128>>>(Q, K, V, Wq, Wk, Wv,
                                              bq, bk, bv, gqt, gkt, gv);

    // vsum + wv on side stream, fully parallel with main; joined before out-proj
    cudaEventRecord(e1, 0);
    cudaStreamWaitEvent(s2, e1, 0);
    vsum_zero_kernel<<<1, BATCH * QKV_N, 0, s2>>>();
    vsum_kernel<<<dim3(BATCH, 16), 256, 0, s2>>>();
    wv_kernel<<<dim3(BATCH, DMODEL / 128), 256, 0, s2>>>(Wo);
    cudaEventRecord(e2, s2);

    // main needs only detect_mask (done long before QKV finished) + QKV outputs
    cudaStreamWaitEvent(0, eDm, 0);
    mab_main_kernel<<<dim3(LQ / BQ, NH, BATCH), 256, SMEM_BYTES>>>(Mk, attn);

    // fork: lse fix-up parallel with out-proj
    cudaEventRecord(e3, 0);
    cudaStreamWaitEvent(s2, e3, 0);
    lse_fix_kernel<<<BATCH * NH * LQ / 2, 256, 0, s2>>>(attn);
    cudaEventRecord(e4, s2);

    cudaStreamWaitEvent(0, e2, 0);   // wv ready (long since done, free)
    gemm_out_kernel<<<dim3(M / 128, DMODEL / 128), 256>>>(gotmp, Wo, bo, out,
                                                          M, QKV_N, DMODEL);
    cudaStreamWaitEvent(0, e4, 0);
}